// round 1
// baseline (speedup 1.0000x reference)
#include <cuda_runtime.h>

// Problem constants
#define S_LEN 2048
#define DIM   64
#define NBH   64          // B*H = 4*16
#define BM    128         // q rows per block
#define BN    64          // k cols per tile
#define NTHREADS 256

// Scratch for row sums (no cudaMalloc allowed)
__device__ float g_rowsum[NBH * S_LEN];

// Fast exp via exp2 polynomial + exponent bit trick. Avoids MUFU entirely
// (268M MUFU ops would cost ~1.9 ms at 0.5 op/cyc/SM).
// Max rel error ~2.5e-6 on the score range (|x| < ~10).
__device__ __forceinline__ float fexp(float x) {
    float t = x * 1.4426950408889634f;          // x * log2(e)
    t = fminf(fmaxf(t, -126.0f), 126.0f);
    float z = t + 12582912.0f;                  // round-to-nearest via 1.5*2^23
    int   j = __float_as_int(z) - 0x4B400000;   // integer part
    float f = t - (z - 12582912.0f);            // frac in [-0.5, 0.5]
    float p =            1.33335581e-3f;
    p = fmaf(p, f, 9.61812910e-3f);
    p = fmaf(p, f, 5.55041087e-2f);
    p = fmaf(p, f, 2.40226507e-1f);
    p = fmaf(p, f, 6.93147180e-1f);
    p = fmaf(p, f, 1.0f);                       // 2^f
    return __int_as_float(__float_as_int(p) + (j << 23));  // * 2^j
}

// Fused attention: per block, 128 q-rows of one (b,h).
// Streams K/V tiles; writes UNNORMALIZED exp(scores) to att_out, accumulates
// rowsums + unnormalized context; context normalized in epilogue; attention
// normalized by a second kernel.
extern "C" __global__ void __launch_bounds__(NTHREADS, 2)
attn_fused(const float* __restrict__ q, const float* __restrict__ k,
           const float* __restrict__ v, const float* __restrict__ mask,
           float* __restrict__ ctx_out, float* __restrict__ att_out) {
    extern __shared__ float sm[];
    float* Qt   = sm;                    // [64][128] d-major (transposed)
    float* Kt   = Qt  + DIM * BM;        // [64][64]  d-major (transposed)
    float* Vs   = Kt  + DIM * BN;        // [64][64]  j-major (natural)
    float* Ps   = Vs  + BN * DIM;        // [64][129] j-major, pitch 129 (bank decorr)
    float* msk  = Ps  + BN * 129;        // [64]
    float* lrow = msk + BN;              // [128]

    const int t  = threadIdx.x;
    const int tx = t & 15;               // col group  (4 cols)
    const int ty = t >> 4;               // row group  (8 rows)
    const int r8 = ty * 8;
    const int c4 = tx * 4;
    const int bh   = blockIdx.y;
    const int b    = bh >> 4;            // H = 16
    const int qoff = blockIdx.x * BM;

    const float* qbase = q + ((size_t)bh * S_LEN + qoff) * DIM;
    const float* kbase = k + (size_t)bh * S_LEN * DIM;
    const float* vbase = v + (size_t)bh * S_LEN * DIM;
    float* attbase = att_out + ((size_t)bh * S_LEN + qoff) * S_LEN;

    // Load Q tile transposed into smem: Qt[d][row]
    for (int idx = t; idx < BM * (DIM / 4); idx += NTHREADS) {
        int row = idx >> 4;
        int dg  = (idx & 15) * 4;
        float4 qv = *(const float4*)(qbase + row * DIM + dg);
        Qt[(dg + 0) * BM + row] = qv.x;
        Qt[(dg + 1) * BM + row] = qv.y;
        Qt[(dg + 2) * BM + row] = qv.z;
        Qt[(dg + 3) * BM + row] = qv.w;
    }

    float ctx[8][4];
    float lp[8];
    #pragma unroll
    for (int r = 0; r < 8; r++) {
        lp[r] = 0.0f;
        #pragma unroll
        for (int c = 0; c < 4; c++) ctx[r][c] = 0.0f;
    }

    for (int kt = 0; kt < S_LEN; kt += BN) {
        __syncthreads();  // previous tile's P·V done before overwriting Kt/Vs/Ps

        // Load K tile transposed (Kt[d][j]) and V tile natural (Vs[j][d])
        for (int idx = t; idx < BN * (DIM / 4); idx += NTHREADS) {
            int row = idx >> 4;
            int dg  = (idx & 15) * 4;
            float4 kv = *(const float4*)(kbase + (size_t)(kt + row) * DIM + dg);
            Kt[(dg + 0) * BN + row] = kv.x;
            Kt[(dg + 1) * BN + row] = kv.y;
            Kt[(dg + 2) * BN + row] = kv.z;
            Kt[(dg + 3) * BN + row] = kv.w;
            float4 vv = *(const float4*)(vbase + (size_t)(kt + row) * DIM + dg);
            *(float4*)(Vs + row * DIM + dg) = vv;
        }
        if (t < BN) msk[t] = mask[b * S_LEN + kt + t];
        __syncthreads();

        // ---- Score GEMM: acc[8][4] = Q_tile · K_tile^T (rank-1 over d) ----
        float acc[8][4];
        #pragma unroll
        for (int r = 0; r < 8; r++)
            #pragma unroll
            for (int c = 0; c < 4; c++) acc[r][c] = 0.0f;

        #pragma unroll 8
        for (int d = 0; d < DIM; ++d) {
            const float4 a0 = *(const float4*)(Qt + d * BM + r8);
            const float4 a1 = *(const float4*)(Qt + d * BM + r8 + 4);
            const float4 bv = *(const float4*)(Kt + d * BN + c4);
            float av[8] = {a0.x, a0.y, a0.z, a0.w, a1.x, a1.y, a1.z, a1.w};
            float bw[4] = {bv.x, bv.y, bv.z, bv.w};
            #pragma unroll
            for (int r = 0; r < 8; r++)
                #pragma unroll
                for (int c = 0; c < 4; c++)
                    acc[r][c] = fmaf(av[r], bw[c], acc[r][c]);
        }

        // ---- Epilogue: p = exp(s*scale + mask); write att; stage Ps; rowsum ----
        float mk[4];
        #pragma unroll
        for (int c = 0; c < 4; c++) mk[c] = msk[c4 + c];

        #pragma unroll
        for (int r = 0; r < 8; r++) {
            float p0 = fexp(fmaf(acc[r][0], 0.125f, mk[0]));
            float p1 = fexp(fmaf(acc[r][1], 0.125f, mk[1]));
            float p2 = fexp(fmaf(acc[r][2], 0.125f, mk[2]));
            float p3 = fexp(fmaf(acc[r][3], 0.125f, mk[3]));
            lp[r] += (p0 + p1) + (p2 + p3);
            int i = r8 + r;
            Ps[(c4 + 0) * 129 + i] = p0;
            Ps[(c4 + 1) * 129 + i] = p1;
            Ps[(c4 + 2) * 129 + i] = p2;
            Ps[(c4 + 3) * 129 + i] = p3;
            float4 o = make_float4(p0, p1, p2, p3);
            *(float4*)(attbase + (size_t)i * S_LEN + kt + c4) = o;
        }
        __syncthreads();

        // ---- P·V GEMM: ctx[8][4] += P_tile · V_tile (rank-1 over j) ----
        #pragma unroll 4
        for (int j = 0; j < BN; ++j) {
            const float4 vv = *(const float4*)(Vs + j * DIM + c4);
            float vw[4] = {vv.x, vv.y, vv.z, vv.w};
            const float* pc = Ps + j * 129 + r8;
            #pragma unroll
            for (int r = 0; r < 8; r++) {
                float pr = pc[r];
                #pragma unroll
                for (int c = 0; c < 4; c++)
                    ctx[r][c] = fmaf(pr, vw[c], ctx[r][c]);
            }
        }
    }

    // ---- Row sums: reduce across the 16 threads (tx) sharing each row ----
    #pragma unroll
    for (int r = 0; r < 8; r++) {
        float s = lp[r];
        #pragma unroll
        for (int off = 1; off < 16; off <<= 1)
            s += __shfl_xor_sync(0xffffffffu, s, off);
        lp[r] = s;
    }
    if (tx == 0) {
        #pragma unroll
        for (int r = 0; r < 8; r++) {
            lrow[r8 + r] = lp[r];
            g_rowsum[(size_t)bh * S_LEN + qoff + r8 + r] = lp[r];
        }
    }
    __syncthreads();

    // ---- Normalized context write ----
    float* cbase = ctx_out + ((size_t)bh * S_LEN + qoff) * DIM;
    #pragma unroll
    for (int r = 0; r < 8; r++) {
        int i = r8 + r;
        float inv = 1.0f / lrow[i];
        float4 o = make_float4(ctx[r][0] * inv, ctx[r][1] * inv,
                               ctx[r][2] * inv, ctx[r][3] * inv);
        *(float4*)(cbase + (size_t)i * DIM + c4) = o;
    }
}

// Normalize attention rows: att[row, :] *= 1/rowsum[row]. Pure bandwidth.
extern "C" __global__ void att_rescale(float* __restrict__ att) {
    const int row = blockIdx.x;                      // 0 .. NBH*S_LEN-1
    const float inv = 1.0f / g_rowsum[row];
    float4* p = (float4*)(att + (size_t)row * S_LEN);
    const int t = threadIdx.x;                       // 128 threads
    #pragma unroll
    for (int i = 0; i < 4; i++) {
        float4 x = p[t + i * 128];
        x.x *= inv; x.y *= inv; x.z *= inv; x.w *= inv;
        p[t + i * 128] = x;
    }
}

extern "C" void kernel_launch(void* const* d_in, const int* in_sizes, int n_in,
                              void* d_out, int out_size) {
    const float* q    = (const float*)d_in[0];
    const float* k    = (const float*)d_in[1];
    const float* v    = (const float*)d_in[2];
    const float* mask = (const float*)d_in[3];
    float* ctx = (float*)d_out;                                  // [B,H,S,D]
    float* att = (float*)d_out + (size_t)NBH * S_LEN * DIM;      // [B,H,S,S]

    const int smem_bytes = (DIM * BM + DIM * BN + BN * DIM + BN * 129 + BN + BM)
                           * (int)sizeof(float);   // 99328
    cudaFuncSetAttribute(attn_fused, cudaFuncAttributeMaxDynamicSharedMemorySize,
                         smem_bytes);

    attn_fused<<<dim3(S_LEN / BM, NBH), NTHREADS, smem_bytes>>>(q, k, v, mask,
                                                                ctx, att);
    att_rescale<<<dim3(NBH * S_LEN), 128>>>(att);
}

// round 3
// speedup vs baseline: 1.7043x; 1.7043x over previous
#include <cuda_runtime.h>
#include <cstdint>

#define S_LEN 2048
#define DIM   64
#define BK    64              // keys per tile
#define NT    (S_LEN / BK)    // 32 tiles
#define SCL   0.18033688011112042f   // 0.125 * log2(e)
#define L2E   1.4426950408889634f

// smem layout (bytes)
#define LDK 68
#define LDV 72
#define LDP 68
#define SM_K    0
#define SM_V    17408          // 64*68*4
#define SM_P    35840          // + 64*72*4
#define SM_MSK  70656          // + 128*68*4
#define SM_TOTAL 70912

__device__ __forceinline__ float tff(float x) {     // round-to-nearest tf32
    uint32_t u;
    asm("cvt.rna.tf32.f32 %0, %1;" : "=r"(u) : "f"(x));
    return __uint_as_float(u);
}

__device__ __forceinline__ float exp2_poly(float t) {
    t = fminf(fmaxf(t, -126.0f), 126.0f);
    float z = t + 12582912.0f;
    int   j = __float_as_int(z) - 0x4B400000;
    float f = t - (z - 12582912.0f);
    float p =            1.33335581e-3f;
    p = fmaf(p, f, 9.61812910e-3f);
    p = fmaf(p, f, 5.55041087e-2f);
    p = fmaf(p, f, 2.40226507e-1f);
    p = fmaf(p, f, 6.93147180e-1f);
    p = fmaf(p, f, 1.0f);
    return __int_as_float(__float_as_int(p) + (j << 23));
}

#define MMA_TF32(d, a, b0, b1)                                               \
    asm volatile("mma.sync.aligned.m16n8k8.row.col.f32.tf32.tf32.f32 "       \
        "{%0,%1,%2,%3}, {%4,%5,%6,%7}, {%8,%9}, {%0,%1,%2,%3};"              \
        : "+f"((d)[0]), "+f"((d)[1]), "+f"((d)[2]), "+f"((d)[3])             \
        : "r"((a)[0]), "r"((a)[1]), "r"((a)[2]), "r"((a)[3]),                \
          "r"(b0), "r"(b1))

// One CTA = 128 q rows of one (b,h); 8 warps, each owns 16 rows.
// Pass 1: rowsums.  Pass 2: normalized attention write + P.V context.
extern "C" __global__ void __launch_bounds__(256, 2)
attn_mma(const float* __restrict__ q, const float* __restrict__ k,
         const float* __restrict__ v, const float* __restrict__ mask,
         float* __restrict__ ctx_out, float* __restrict__ att_out) {
    extern __shared__ char sm[];
    float* Ks = (float*)(sm + SM_K);    // [64 key][68]  (d contiguous)
    float* Vs = (float*)(sm + SM_V);    // [64 key][72]
    float* Ps = (float*)(sm + SM_P);    // [128 row][68] warp-private slices
    float* Ms = (float*)(sm + SM_MSK);  // [64] mask * log2e

    const int tid  = threadIdx.x;
    const int wid  = tid >> 5, lane = tid & 31;
    const int r    = lane >> 2, c = lane & 3;
    const int bh   = blockIdx.y, b = bh >> 4;
    const int qoff = blockIdx.x * 128;
    const int wrow = qoff + wid * 16;

    // ---- Q A-fragments, persistent, pre-scaled, tf32 ----
    const float* qb = q + ((size_t)bh * S_LEN + wrow) * DIM;
    uint32_t qa[8][4];
    #pragma unroll
    for (int kk = 0; kk < 8; ++kk) {
        qa[kk][0] = __float_as_uint(tff(qb[(size_t)r       * DIM + 8*kk + c    ] * SCL));
        qa[kk][1] = __float_as_uint(tff(qb[(size_t)(r + 8) * DIM + 8*kk + c    ] * SCL));
        qa[kk][2] = __float_as_uint(tff(qb[(size_t)r       * DIM + 8*kk + c + 4] * SCL));
        qa[kk][3] = __float_as_uint(tff(qb[(size_t)(r + 8) * DIM + 8*kk + c + 4] * SCL));
    }

    const float* kb = k + (size_t)bh * S_LEN * DIM;
    const float* vb = v + (size_t)bh * S_LEN * DIM;

    float rs0 = 0.0f, rs1 = 0.0f;

    // ================= pass 1: rowsums =================
    for (int t = 0; t < NT; ++t) {
        __syncthreads();
        for (int i = tid; i < BK * (DIM / 4); i += 256) {
            int key = i >> 4, dg = (i & 15) * 4;
            float4 x = *(const float4*)(kb + (size_t)(t * BK + key) * DIM + dg);
            float* dst = Ks + key * LDK + dg;
            dst[0] = tff(x.x); dst[1] = tff(x.y); dst[2] = tff(x.z); dst[3] = tff(x.w);
        }
        if (tid < BK) Ms[tid] = mask[b * S_LEN + t * BK + tid] * L2E;
        __syncthreads();

        float sc[8][4] = {};
        #pragma unroll
        for (int kk = 0; kk < 8; ++kk)
            #pragma unroll
            for (int ns = 0; ns < 8; ++ns) {
                uint32_t b0 = __float_as_uint(Ks[(8*ns + r) * LDK + 8*kk + c    ]);
                uint32_t b1 = __float_as_uint(Ks[(8*ns + r) * LDK + 8*kk + c + 4]);
                MMA_TF32(sc[ns], qa[kk], b0, b1);
            }
        #pragma unroll
        for (int ns = 0; ns < 8; ++ns) {
            float m0 = Ms[8*ns + 2*c], m1 = Ms[8*ns + 2*c + 1];
            rs0 += exp2_poly(sc[ns][0] + m0) + exp2_poly(sc[ns][1] + m1);
            rs1 += exp2_poly(sc[ns][2] + m0) + exp2_poly(sc[ns][3] + m1);
        }
    }
    rs0 += __shfl_xor_sync(0xffffffffu, rs0, 1);
    rs0 += __shfl_xor_sync(0xffffffffu, rs0, 2);
    rs1 += __shfl_xor_sync(0xffffffffu, rs1, 1);
    rs1 += __shfl_xor_sync(0xffffffffu, rs1, 2);
    const float inv0 = 1.0f / rs0, inv1 = 1.0f / rs1;

    // ================= pass 2: att + ctx =================
    float cx[8][4] = {};
    float* Pw   = Ps + (wid * 16) * LDP;          // warp-private P slice
    float* attb = att_out + ((size_t)bh * S_LEN + wrow) * S_LEN;

    for (int t = 0; t < NT; ++t) {
        __syncthreads();
        for (int i = tid; i < BK * (DIM / 4); i += 256) {
            int key = i >> 4, dg = (i & 15) * 4;
            float4 x = *(const float4*)(kb + (size_t)(t * BK + key) * DIM + dg);
            float* dk = Ks + key * LDK + dg;
            dk[0] = tff(x.x); dk[1] = tff(x.y); dk[2] = tff(x.z); dk[3] = tff(x.w);
            float4 y = *(const float4*)(vb + (size_t)(t * BK + key) * DIM + dg);
            float* dv = Vs + key * LDV + dg;
            dv[0] = tff(y.x); dv[1] = tff(y.y); dv[2] = tff(y.z); dv[3] = tff(y.w);
        }
        if (tid < BK) Ms[tid] = mask[b * S_LEN + t * BK + tid] * L2E;
        __syncthreads();

        float sc[8][4] = {};
        #pragma unroll
        for (int kk = 0; kk < 8; ++kk)
            #pragma unroll
            for (int ns = 0; ns < 8; ++ns) {
                uint32_t b0 = __float_as_uint(Ks[(8*ns + r) * LDK + 8*kk + c    ]);
                uint32_t b1 = __float_as_uint(Ks[(8*ns + r) * LDK + 8*kk + c + 4]);
                MMA_TF32(sc[ns], qa[kk], b0, b1);
            }

        // epilogue: normalized exp -> att store + P stage (tf32)
        #pragma unroll
        for (int ns = 0; ns < 8; ++ns) {
            float m0 = Ms[8*ns + 2*c], m1 = Ms[8*ns + 2*c + 1];
            float e0 = exp2_poly(sc[ns][0] + m0) * inv0;
            float e1 = exp2_poly(sc[ns][1] + m1) * inv0;
            float e2 = exp2_poly(sc[ns][2] + m0) * inv1;
            float e3 = exp2_poly(sc[ns][3] + m1) * inv1;
            int col = t * BK + 8*ns + 2*c;
            *(float2*)(attb + (size_t)r       * S_LEN + col) = make_float2(e0, e1);
            *(float2*)(attb + (size_t)(r + 8) * S_LEN + col) = make_float2(e2, e3);
            *(float2*)(Pw + r       * LDP + 8*ns + 2*c) = make_float2(tff(e0), tff(e1));
            *(float2*)(Pw + (r + 8) * LDP + 8*ns + 2*c) = make_float2(tff(e2), tff(e3));
        }
        __syncwarp();

        // P.V : cx[ns] += P(16x64) * V(64x64)
        #pragma unroll
        for (int kk = 0; kk < 8; ++kk) {
            uint32_t pa[4];
            pa[0] = __float_as_uint(Pw[r       * LDP + 8*kk + c    ]);
            pa[1] = __float_as_uint(Pw[(r + 8) * LDP + 8*kk + c    ]);
            pa[2] = __float_as_uint(Pw[r       * LDP + 8*kk + c + 4]);
            pa[3] = __float_as_uint(Pw[(r + 8) * LDP + 8*kk + c + 4]);
            #pragma unroll
            for (int ns = 0; ns < 8; ++ns) {
                uint32_t b0 = __float_as_uint(Vs[(8*kk + c    ) * LDV + 8*ns + r]);
                uint32_t b1 = __float_as_uint(Vs[(8*kk + c + 4) * LDV + 8*ns + r]);
                MMA_TF32(cx[ns], pa, b0, b1);
            }
        }
    }

    // ---- context write (already normalized; P was normalized) ----
    float* cb = ctx_out + ((size_t)bh * S_LEN + wrow) * DIM;
    #pragma unroll
    for (int ns = 0; ns < 8; ++ns) {
        *(float2*)(cb + (size_t)r       * DIM + 8*ns + 2*c) = make_float2(cx[ns][0], cx[ns][1]);
        *(float2*)(cb + (size_t)(r + 8) * DIM + 8*ns + 2*c) = make_float2(cx[ns][2], cx[ns][3]);
    }
}

extern "C" void kernel_launch(void* const* d_in, const int* in_sizes, int n_in,
                              void* d_out, int out_size) {
    const float* q    = (const float*)d_in[0];
    const float* k    = (const float*)d_in[1];
    const float* v    = (const float*)d_in[2];
    const float* mask = (const float*)d_in[3];
    float* ctx = (float*)d_out;                                   // [B,H,S,D]
    float* att = (float*)d_out + (size_t)64 * S_LEN * DIM;        // [B,H,S,S]

    cudaFuncSetAttribute(attn_mma, cudaFuncAttributeMaxDynamicSharedMemorySize,
                         SM_TOTAL);
    attn_mma<<<dim3(S_LEN / 128, 64), 256, SM_TOTAL>>>(q, k, v, mask, ctx, att);
}

// round 5
// speedup vs baseline: 1.7077x; 1.0020x over previous
#include <cuda_runtime.h>
#include <cstdint>

#define S_LEN 2048
#define DIM   64
#define BK    64
#define NT    (S_LEN / BK)    // 32
#define SCL   0.18033688011112042f   // 0.125 * log2(e)
#define L2E   1.4426950408889634f

// smem layout in floats
#define QF_OFF 0              // 8 warps * 32 lanes * 36 = 9216
#define KF_OFF 9216           // 8 ns * 640              = 5120
#define VF_OFF 14336          // 8 ns * 640              = 5120
#define PF_OFF 19456          // 8 warps * 32 lanes * 36 = 9216
#define MS_OFF 28672          // 64
#define SM_FLOATS 28736
#define SM_BYTES  (SM_FLOATS * 4)   // 114944

__device__ __forceinline__ float tff(float x) {     // round-to-nearest tf32
    uint32_t u;
    asm("cvt.rna.tf32.f32 %0, %1;" : "=r"(u) : "f"(x));
    return __uint_as_float(u);
}

__device__ __forceinline__ float exp2_poly(float t) {
    float z = t + 12582912.0f;
    int   j = __float_as_int(z) - 0x4B400000;
    float f = t - (z - 12582912.0f);
    float p =            1.33335581e-3f;
    p = fmaf(p, f, 9.61812910e-3f);
    p = fmaf(p, f, 5.55041087e-2f);
    p = fmaf(p, f, 2.40226507e-1f);
    p = fmaf(p, f, 6.93147180e-1f);
    p = fmaf(p, f, 1.0f);
    return __int_as_float(__float_as_int(p) + (j << 23));
}

#define MMA_TF32(d, a, b0, b1)                                               \
    asm volatile("mma.sync.aligned.m16n8k8.row.col.f32.tf32.tf32.f32 "       \
        "{%0,%1,%2,%3}, {%4,%5,%6,%7}, {%8,%9}, {%0,%1,%2,%3};"              \
        : "+f"((d)[0]), "+f"((d)[1]), "+f"((d)[2]), "+f"((d)[3])             \
        : "r"((a)[0]), "r"((a)[1]), "r"((a)[2]), "r"((a)[3]),                \
          "r"(b0), "r"(b1))

// Kf: slot[(ns*32 + ((key&7)<<2|(d&3)))*20 + (d>>3)*2 + ((d>>2)&1)] = tf32 K[key][d]
__device__ __forceinline__ void scatter_k(float* sm, int i, float4 x) {
    int key = i >> 4, dg4 = i & 15;
    int ns = key >> 3, lr = key & 7;
    float vv[4] = {x.x, x.y, x.z, x.w};
    #pragma unroll
    for (int j = 0; j < 4; ++j) {
        int d = dg4 * 4 + j;
        int kk = d >> 3, h = (d >> 2) & 1, c = d & 3;
        sm[KF_OFF + ns * 640 + (((lr << 2) | c)) * 20 + kk * 2 + h] = tff(vv[j]);
    }
}
// Vf: slot[ns*640 + (((d&7)<<2)|(key&3))*20 + (key>>3)*2 + ((key>>2)&1)] = tf32 V[key][d]
__device__ __forceinline__ void scatter_v(float* sm, int i, float4 x) {
    int key = i >> 4, dg4 = i & 15;
    int kk = key >> 3, c = key & 3, h = (key >> 2) & 1;
    float vv[4] = {x.x, x.y, x.z, x.w};
    #pragma unroll
    for (int j = 0; j < 4; ++j) {
        int d = dg4 * 4 + j;
        int ns = d >> 3, rr = d & 7;
        sm[VF_OFF + ns * 640 + (((rr << 2) | c)) * 20 + kk * 2 + h] = tff(vv[j]);
    }
}

extern "C" __global__ void __launch_bounds__(256, 2)
attn_mma(const float* __restrict__ q, const float* __restrict__ k,
         const float* __restrict__ v, const float* __restrict__ mask,
         float* __restrict__ ctx_out, float* __restrict__ att_out) {
    extern __shared__ float sm[];
    const int tid = threadIdx.x, wid = tid >> 5, lane = tid & 31;
    const int r = lane >> 2, c = lane & 3;
    const int bh = blockIdx.y, b = bh >> 4;
    const int qoff = blockIdx.x * 128;
    const int wrow = qoff + wid * 16;

    const float* kb = k + (size_t)bh * S_LEN * DIM;
    const float* vb = v + (size_t)bh * S_LEN * DIM;
    const float* mb = mask + b * S_LEN;

    // ---- prologue: Qf (fragment-ready, pre-scaled tf32) + tile0 K + mask ----
    {
        const float* qb = q + ((size_t)bh * S_LEN + qoff) * DIM;
        for (int i = tid; i < 128 * 16; i += 256) {
            int row = i >> 4, dg4 = i & 15;
            float4 x = *(const float4*)(qb + row * DIM + dg4 * 4);
            int w = row >> 4, rl = row & 15;
            float vv[4] = {x.x, x.y, x.z, x.w};
            #pragma unroll
            for (int j = 0; j < 4; ++j) {
                int d = dg4 * 4 + j;
                int kk = d >> 3, ch = d & 7;
                int jf = ((ch >> 2) << 1) | (rl >> 3);
                int ln = ((rl & 7) << 2) | (ch & 3);
                sm[QF_OFF + w * 1152 + ln * 36 + kk * 4 + jf] = tff(vv[j] * SCL);
            }
        }
        for (int i = tid; i < 1024; i += 256)
            scatter_k(sm, i, *(const float4*)(kb + (size_t)(i >> 4) * DIM + (i & 15) * 4));
        if (tid < 64) sm[MS_OFF + tid] = mb[tid] * L2E;
    }
    __syncthreads();

    const float* Qw = sm + QF_OFF + wid * 1152 + lane * 36;

    float rs0 = 0.0f, rs1 = 0.0f;

    // ================= pass 1: rowsums =================
    for (int t = 0; t < NT; ++t) {
        const bool more = (t + 1 < NT);
        float4 kr[4]; float mr = 0.0f;
        if (more) {
            #pragma unroll
            for (int it = 0; it < 4; ++it) {
                int i = tid + it * 256;
                kr[it] = *(const float4*)(kb + ((size_t)(t + 1) * BK + (i >> 4)) * DIM + (i & 15) * 4);
            }
            if (tid < 64) mr = mb[(t + 1) * BK + tid];
        }
        float sc[8][4] = {};
        #pragma unroll
        for (int i = 0; i < 4; ++i) {
            uint4 qa0 = *(const uint4*)(Qw + 8 * i);
            uint4 qa1 = *(const uint4*)(Qw + 8 * i + 4);
            #pragma unroll
            for (int ns = 0; ns < 8; ++ns) {
                float4 bb = *(const float4*)(sm + KF_OFF + ns * 640 + lane * 20 + 4 * i);
                MMA_TF32(sc[ns], (&qa0.x), __float_as_uint(bb.x), __float_as_uint(bb.y));
                MMA_TF32(sc[ns], (&qa1.x), __float_as_uint(bb.z), __float_as_uint(bb.w));
            }
        }
        const float2* Ms2 = (const float2*)(sm + MS_OFF);
        #pragma unroll
        for (int ns = 0; ns < 8; ++ns) {
            float2 mm = Ms2[ns * 4 + c];
            rs0 += exp2_poly(sc[ns][0] + mm.x) + exp2_poly(sc[ns][1] + mm.y);
            rs1 += exp2_poly(sc[ns][2] + mm.x) + exp2_poly(sc[ns][3] + mm.y);
        }
        __syncthreads();
        if (more) {
            #pragma unroll
            for (int it = 0; it < 4; ++it) scatter_k(sm, tid + it * 256, kr[it]);
            if (tid < 64) sm[MS_OFF + tid] = mr * L2E;
        }
        __syncthreads();
    }
    rs0 += __shfl_xor_sync(0xffffffffu, rs0, 1);
    rs0 += __shfl_xor_sync(0xffffffffu, rs0, 2);
    rs1 += __shfl_xor_sync(0xffffffffu, rs1, 1);
    rs1 += __shfl_xor_sync(0xffffffffu, rs1, 2);
    const float inv0 = 1.0f / rs0, inv1 = 1.0f / rs1;

    // ---- reload tile 0 (K + V + mask) ----
    for (int i = tid; i < 1024; i += 256) {
        size_t off = (size_t)(i >> 4) * DIM + (i & 15) * 4;
        scatter_k(sm, i, *(const float4*)(kb + off));
        scatter_v(sm, i, *(const float4*)(vb + off));
    }
    if (tid < 64) sm[MS_OFF + tid] = mb[tid] * L2E;
    __syncthreads();

    // ================= pass 2: att + ctx =================
    float cx[8][4] = {};
    float* Pfw = sm + PF_OFF + wid * 1152;       // warp's fragment-ready P
    const float* Pfl = Pfw + lane * 36;
    // per-lane scatter bases for the C->A fragment permutation
    const int c2 = 2 * c;
    float* Pw0 = Pfw + (((r << 2) | (c2 & 3)) * 36)       + (((c2 >> 2) & 1) * 2);
    float* Pw1 = Pfw + (((r << 2) | ((c2 + 1) & 3)) * 36) + ((((c2 + 1) >> 2) & 1) * 2);
    float* attb = att_out + ((size_t)bh * S_LEN + wrow) * S_LEN;

    for (int t = 0; t < NT; ++t) {
        const bool more = (t + 1 < NT);
        float4 kr[4], vr[4]; float mr = 0.0f;
        if (more) {
            #pragma unroll
            for (int it = 0; it < 4; ++it) {
                int i = tid + it * 256;
                size_t off = ((size_t)(t + 1) * BK + (i >> 4)) * DIM + (i & 15) * 4;
                kr[it] = *(const float4*)(kb + off);
                vr[it] = *(const float4*)(vb + off);
            }
            if (tid < 64) mr = mb[(t + 1) * BK + tid];
        }
        float sc[8][4] = {};
        #pragma unroll
        for (int i = 0; i < 4; ++i) {
            uint4 qa0 = *(const uint4*)(Qw + 8 * i);
            uint4 qa1 = *(const uint4*)(Qw + 8 * i + 4);
            #pragma unroll
            for (int ns = 0; ns < 8; ++ns) {
                float4 bb = *(const float4*)(sm + KF_OFF + ns * 640 + lane * 20 + 4 * i);
                MMA_TF32(sc[ns], (&qa0.x), __float_as_uint(bb.x), __float_as_uint(bb.y));
                MMA_TF32(sc[ns], (&qa1.x), __float_as_uint(bb.z), __float_as_uint(bb.w));
            }
        }
        // epilogue: normalized exp -> att store (from regs) + P fragment scatter
        const float2* Ms2 = (const float2*)(sm + MS_OFF);
        #pragma unroll
        for (int ns = 0; ns < 8; ++ns) {
            float2 mm = Ms2[ns * 4 + c];
            float e0 = exp2_poly(sc[ns][0] + mm.x) * inv0;
            float e1 = exp2_poly(sc[ns][1] + mm.y) * inv0;
            float e2 = exp2_poly(sc[ns][2] + mm.x) * inv1;
            float e3 = exp2_poly(sc[ns][3] + mm.y) * inv1;
            int col = t * BK + 8 * ns + c2;
            *(float2*)(attb + (size_t)r * S_LEN + col)       = make_float2(e0, e1);
            *(float2*)(attb + (size_t)(r + 8) * S_LEN + col) = make_float2(e2, e3);
            *(float2*)(Pw0 + ns * 4) = make_float2(tff(e0), tff(e2));
            *(float2*)(Pw1 + ns * 4) = make_float2(tff(e1), tff(e3));
        }
        __syncwarp();
        // P.V : cx[ns] += P(16x64) * V(64x64), A-frags via LDS.128
        #pragma unroll
        for (int i = 0; i < 4; ++i) {
            uint4 pa0 = *(const uint4*)(Pfl + 8 * i);       // kkv = 2i
            uint4 pa1 = *(const uint4*)(Pfl + 8 * i + 4);   // kkv = 2i+1
            #pragma unroll
            for (int ns = 0; ns < 8; ++ns) {
                float4 bb = *(const float4*)(sm + VF_OFF + ns * 640 + lane * 20 + 4 * i);
                MMA_TF32(cx[ns], (&pa0.x), __float_as_uint(bb.x), __float_as_uint(bb.y));
                MMA_TF32(cx[ns], (&pa1.x), __float_as_uint(bb.z), __float_as_uint(bb.w));
            }
        }
        __syncthreads();
        if (more) {
            #pragma unroll
            for (int it = 0; it < 4; ++it) {
                scatter_k(sm, tid + it * 256, kr[it]);
                scatter_v(sm, tid + it * 256, vr[it]);
            }
            if (tid < 64) sm[MS_OFF + tid] = mr * L2E;
        }
        __syncthreads();
    }

    // ---- context write (P was normalized -> already final) ----
    float* cb = ctx_out + ((size_t)bh * S_LEN + wrow) * DIM;
    #pragma unroll
    for (int ns = 0; ns < 8; ++ns) {
        *(float2*)(cb + (size_t)r * DIM + ns * 8 + c2)       = make_float2(cx[ns][0], cx[ns][1]);
        *(float2*)(cb + (size_t)(r + 8) * DIM + ns * 8 + c2) = make_float2(cx[ns][2], cx[ns][3]);
    }
}

extern "C" void kernel_launch(void* const* d_in, const int* in_sizes, int n_in,
                              void* d_out, int out_size) {
    const float* q    = (const float*)d_in[0];
    const float* k    = (const float*)d_in[1];
    const float* v    = (const float*)d_in[2];
    const float* mask = (const float*)d_in[3];
    float* ctx = (float*)d_out;                                   // [B,H,S,D]
    float* att = (float*)d_out + (size_t)64 * S_LEN * DIM;        // [B,H,S,S]

    cudaFuncSetAttribute(attn_mma, cudaFuncAttributeMaxDynamicSharedMemorySize,
                         SM_BYTES);
    attn_mma<<<dim3(S_LEN / 128, 64), 256, SM_BYTES>>>(q, k, v, mask, ctx, att);
}

// round 6
// speedup vs baseline: 1.8769x; 1.0991x over previous
#include <cuda_runtime.h>
#include <cstdint>

#define S_LEN 2048
#define DIM   64
#define NT    32                      // 64-key tiles
#define SCL   0.18033688011112042f    // 0.125 * log2(e)
#define L2E   1.4426950408889634f

// smem layout (float offsets)
#define KF(b)   ((b) * 5120)          // K frags, double buffer
#define VF(b)   (10240 + (b) * 5120)  // V frags, double buffer
#define PW_OFF  20480                 // P row-staging: 8 warps * 32 rows * 20
#define MS(b)   (25600 + (b) * 64)    // mask * log2e, double buffer
#define SM_FLOATS 25728
#define SM_BYTES  (SM_FLOATS * 4)     // 102912

__device__ __forceinline__ float tff(float x) {      // round-to-nearest tf32
    uint32_t u;
    asm("cvt.rna.tf32.f32 %0, %1;" : "=r"(u) : "f"(x));
    return __uint_as_float(u);
}

__device__ __forceinline__ float exp2_poly(float t) {
    float z = t + 12582912.0f;
    int   j = __float_as_int(z) - 0x4B400000;
    float f = t - (z - 12582912.0f);
    float p =            1.33335581e-3f;
    p = fmaf(p, f, 9.61812910e-3f);
    p = fmaf(p, f, 5.55041087e-2f);
    p = fmaf(p, f, 2.40226507e-1f);
    p = fmaf(p, f, 6.93147180e-1f);
    p = fmaf(p, f, 1.0f);
    return __int_as_float(__float_as_int(p) + (j << 23));
}

#define MMA_TF32(d, a, b0, b1)                                               \
    asm volatile("mma.sync.aligned.m16n8k8.row.col.f32.tf32.tf32.f32 "       \
        "{%0,%1,%2,%3}, {%4,%5,%6,%7}, {%8,%9}, {%0,%1,%2,%3};"              \
        : "+f"((d)[0]), "+f"((d)[1]), "+f"((d)[2]), "+f"((d)[3])             \
        : "r"((a)[0]), "r"((a)[1]), "r"((a)[2]), "r"((a)[3]),                \
          "r"(b0), "r"(b1))

// Kf: base[ns*640 + ((key&7)<<2 | d&3)*20 + (d>>3)*2 + ((d>>2)&1)] = tf32 K[key][d]
__device__ __forceinline__ void scatter_k(float* base, int i, float4 x) {
    int key = i >> 4, dg4 = i & 15;
    int ns = key >> 3, lr = key & 7;
    float vv[4] = {x.x, x.y, x.z, x.w};
    #pragma unroll
    for (int j = 0; j < 4; ++j) {
        int d = dg4 * 4 + j;
        int kk = d >> 3, h = (d >> 2) & 1, cc = d & 3;
        base[ns * 640 + ((lr << 2) | cc) * 20 + kk * 2 + h] = tff(vv[j]);
    }
}
// Vf: base[(d>>3)*640 + ((d&7)<<2 | key&3)*20 + (key>>3)*2 + ((key>>2)&1)] = tf32 V[key][d]
__device__ __forceinline__ void scatter_v(float* base, int i, float4 x) {
    int key = i >> 4, dg4 = i & 15;
    int kk = key >> 3, cc = key & 3, h = (key >> 2) & 1;
    float vv[4] = {x.x, x.y, x.z, x.w};
    #pragma unroll
    for (int j = 0; j < 4; ++j) {
        int d = dg4 * 4 + j;
        int ns = d >> 3, rr = d & 7;
        base[ns * 640 + ((rr << 2) | cc) * 20 + kk * 2 + h] = tff(vv[j]);
    }
}

// One CTA = 256 q rows of one (b,h); 8 warps x 32 rows.
// Phase 1: QK -> exp -> unnormalized att + rowsums.
// Phase 2: read att back, normalize (rewrite), P.V -> ctx.
extern "C" __global__ void __launch_bounds__(256, 2)
attn_mma(const float* __restrict__ q, const float* __restrict__ k,
         const float* __restrict__ v, const float* __restrict__ mask,
         float* __restrict__ ctx_out, float* __restrict__ att_out) {
    extern __shared__ float sm[];
    const int tid = threadIdx.x, wid = tid >> 5, lane = tid & 31;
    const int r = lane >> 2, c = lane & 3;
    const int bh = blockIdx.y, b = bh >> 4;
    const int qoff = blockIdx.x * 256;

    const float* kb = k + (size_t)bh * S_LEN * DIM;
    const float* vb = v + (size_t)bh * S_LEN * DIM;
    const float* mb = mask + b * S_LEN;
    float* attw = att_out + ((size_t)bh * S_LEN + qoff + wid * 32) * S_LEN;

    // ---- Q fragments, persistent (2 rowfrags x 8 k-steps), pre-scaled tf32 ----
    uint32_t qa[2][8][4];
    {
        const float* qb = q + ((size_t)bh * S_LEN + qoff + wid * 32) * DIM;
        #pragma unroll
        for (int g = 0; g < 2; ++g)
            #pragma unroll
            for (int kk = 0; kk < 8; ++kk) {
                qa[g][kk][0] = __float_as_uint(tff(qb[(16 * g + r)     * DIM + 8 * kk + c]     * SCL));
                qa[g][kk][1] = __float_as_uint(tff(qb[(16 * g + 8 + r) * DIM + 8 * kk + c]     * SCL));
                qa[g][kk][2] = __float_as_uint(tff(qb[(16 * g + r)     * DIM + 8 * kk + c + 4] * SCL));
                qa[g][kk][3] = __float_as_uint(tff(qb[(16 * g + 8 + r) * DIM + 8 * kk + c + 4] * SCL));
            }
    }

    // ---- tile 0 K + mask ----
    for (int i = tid; i < 1024; i += 256)
        scatter_k(sm + KF(0), i, *(const float4*)(kb + (size_t)(i >> 4) * DIM + (i & 15) * 4));
    if (tid < 64) sm[MS(0) + tid] = mb[tid] * L2E;
    __syncthreads();

    float rs[2][2] = {};

    // ================= phase 1: QK + exp -> unnormalized att + rowsums =================
    for (int t = 0; t < NT; ++t) {
        const int p = t & 1;
        const bool more = (t + 1 < NT);
        float4 kr[4]; float mr = 0.0f;
        if (more) {
            #pragma unroll
            for (int it = 0; it < 4; ++it) {
                int i = tid + it * 256;
                kr[it] = *(const float4*)(kb + ((size_t)(t + 1) * 64 + (i >> 4)) * DIM + (i & 15) * 4);
            }
            if (tid < 64) mr = mb[(t + 1) * 64 + tid];
        }
        #pragma unroll
        for (int half = 0; half < 2; ++half) {
            #pragma unroll
            for (int ns = half * 4; ns < half * 4 + 4; ++ns) {
                float sc0[4] = {}, sc1[4] = {};
                #pragma unroll
                for (int i = 0; i < 4; ++i) {
                    float4 bb = *(const float4*)(sm + KF(p) + ns * 640 + lane * 20 + 4 * i);
                    MMA_TF32(sc0, qa[0][2 * i],     __float_as_uint(bb.x), __float_as_uint(bb.y));
                    MMA_TF32(sc0, qa[0][2 * i + 1], __float_as_uint(bb.z), __float_as_uint(bb.w));
                    MMA_TF32(sc1, qa[1][2 * i],     __float_as_uint(bb.x), __float_as_uint(bb.y));
                    MMA_TF32(sc1, qa[1][2 * i + 1], __float_as_uint(bb.z), __float_as_uint(bb.w));
                }
                float2 mm = ((const float2*)(sm + MS(p)))[ns * 4 + c];
                int col = t * 64 + 8 * ns + 2 * c;
                {
                    float e0 = exp2_poly(sc0[0] + mm.x), e1 = exp2_poly(sc0[1] + mm.y);
                    float e2 = exp2_poly(sc0[2] + mm.x), e3 = exp2_poly(sc0[3] + mm.y);
                    rs[0][0] += e0 + e1; rs[0][1] += e2 + e3;
                    *(float2*)(attw + (size_t)r       * S_LEN + col) = make_float2(e0, e1);
                    *(float2*)(attw + (size_t)(8 + r) * S_LEN + col) = make_float2(e2, e3);
                }
                {
                    float e0 = exp2_poly(sc1[0] + mm.x), e1 = exp2_poly(sc1[1] + mm.y);
                    float e2 = exp2_poly(sc1[2] + mm.x), e3 = exp2_poly(sc1[3] + mm.y);
                    rs[1][0] += e0 + e1; rs[1][1] += e2 + e3;
                    *(float2*)(attw + (size_t)(16 + r) * S_LEN + col) = make_float2(e0, e1);
                    *(float2*)(attw + (size_t)(24 + r) * S_LEN + col) = make_float2(e2, e3);
                }
            }
            if (half == 0 && more) {
                #pragma unroll
                for (int it = 0; it < 4; ++it) scatter_k(sm + KF(1 - p), tid + it * 256, kr[it]);
                if (tid < 64) sm[MS(1 - p) + tid] = mr * L2E;
            }
        }
        __syncthreads();
    }

    // ---- per-lane inverse rowsums (lane->row map identical in phase 2) ----
    float inv[4];
    #pragma unroll
    for (int g = 0; g < 2; ++g)
        #pragma unroll
        for (int b2 = 0; b2 < 2; ++b2) {
            float s = rs[g][b2];
            s += __shfl_xor_sync(0xffffffffu, s, 1);
            s += __shfl_xor_sync(0xffffffffu, s, 2);
            inv[2 * g + b2] = 1.0f / s;
        }

    // ---- tile 0 V ----
    for (int i = tid; i < 1024; i += 256)
        scatter_v(sm + VF(0), i, *(const float4*)(vb + (size_t)(i >> 4) * DIM + (i & 15) * 4));
    __syncthreads();

    // ================= phase 2: normalize att (RMW) + P.V =================
    float cx[2][8][4] = {};
    float* Pst = sm + PW_OFF + wid * 640;     // [32 rows][20], conflict-free

    for (int t = 0; t < NT; ++t) {
        const int p = t & 1;
        const bool more = (t + 1 < NT);
        float4 vr[4];
        if (more) {
            #pragma unroll
            for (int it = 0; it < 4; ++it) {
                int i = tid + it * 256;
                vr[it] = *(const float4*)(vb + ((size_t)(t + 1) * 64 + (i >> 4)) * DIM + (i & 15) * 4);
            }
        }
        #pragma unroll
        for (int half = 0; half < 2; ++half) {
            #pragma unroll
            for (int i4 = half * 2; i4 < half * 2 + 2; ++i4) {
                // load att slice (32 rows x 16 keys), normalize, rewrite, stage tf32
                #pragma unroll
                for (int j = 0; j < 4; ++j) {
                    float* gp = attw + (size_t)(8 * j + r) * S_LEN + t * 64 + i4 * 16 + 4 * c;
                    float4 x = *(const float4*)gp;
                    x.x *= inv[j]; x.y *= inv[j]; x.z *= inv[j]; x.w *= inv[j];
                    *(float4*)gp = x;
                    float4 xt = make_float4(tff(x.x), tff(x.y), tff(x.z), tff(x.w));
                    *(float4*)(Pst + (8 * j + r) * 20 + 4 * c) = xt;
                }
                __syncwarp();
                // gather A-frags for both rowfrags, k-steps 2*i4, 2*i4+1
                uint32_t pa[2][2][4];
                #pragma unroll
                for (int g = 0; g < 2; ++g)
                    #pragma unroll
                    for (int kl = 0; kl < 2; ++kl) {
                        pa[g][kl][0] = __float_as_uint(Pst[(g * 16 + r)     * 20 + kl * 8 + c]);
                        pa[g][kl][1] = __float_as_uint(Pst[(g * 16 + 8 + r) * 20 + kl * 8 + c]);
                        pa[g][kl][2] = __float_as_uint(Pst[(g * 16 + r)     * 20 + kl * 8 + c + 4]);
                        pa[g][kl][3] = __float_as_uint(Pst[(g * 16 + 8 + r) * 20 + kl * 8 + c + 4]);
                    }
                #pragma unroll
                for (int nsv = 0; nsv < 8; ++nsv) {
                    float4 bb = *(const float4*)(sm + VF(p) + nsv * 640 + lane * 20 + 4 * i4);
                    MMA_TF32(cx[0][nsv], pa[0][0], __float_as_uint(bb.x), __float_as_uint(bb.y));
                    MMA_TF32(cx[0][nsv], pa[0][1], __float_as_uint(bb.z), __float_as_uint(bb.w));
                    MMA_TF32(cx[1][nsv], pa[1][0], __float_as_uint(bb.x), __float_as_uint(bb.y));
                    MMA_TF32(cx[1][nsv], pa[1][1], __float_as_uint(bb.z), __float_as_uint(bb.w));
                }
                __syncwarp();   // staging buffer reused next group
            }
            if (half == 0 && more) {
                #pragma unroll
                for (int it = 0; it < 4; ++it) scatter_v(sm + VF(1 - p), tid + it * 256, vr[it]);
            }
        }
        __syncthreads();
    }

    // ---- context write (P was normalized -> final) ----
    float* cb = ctx_out + ((size_t)bh * S_LEN + qoff + wid * 32) * DIM;
    #pragma unroll
    for (int g = 0; g < 2; ++g)
        #pragma unroll
        for (int nsv = 0; nsv < 8; ++nsv) {
            *(float2*)(cb + (size_t)(16 * g + r)     * DIM + 8 * nsv + 2 * c) = make_float2(cx[g][nsv][0], cx[g][nsv][1]);
            *(float2*)(cb + (size_t)(16 * g + 8 + r) * DIM + 8 * nsv + 2 * c) = make_float2(cx[g][nsv][2], cx[g][nsv][3]);
        }
}

extern "C" void kernel_launch(void* const* d_in, const int* in_sizes, int n_in,
                              void* d_out, int out_size) {
    const float* q    = (const float*)d_in[0];
    const float* k    = (const float*)d_in[1];
    const float* v    = (const float*)d_in[2];
    const float* mask = (const float*)d_in[3];
    float* ctx = (float*)d_out;                                   // [B,H,S,D]
    float* att = (float*)d_out + (size_t)64 * S_LEN * DIM;        // [B,H,S,S]

    cudaFuncSetAttribute(attn_mma, cudaFuncAttributeMaxDynamicSharedMemorySize,
                         SM_BYTES);
    attn_mma<<<dim3(S_LEN / 256, 64), 256, SM_BYTES>>>(q, k, v, mask, ctx, att);
}